// round 16
// baseline (speedup 1.0000x reference)
#include <cuda_runtime.h>
#include <cuda_fp16.h>
#include <cstdint>
#include <math.h>

#define HH 56
#define WW 56
#define NB 16
#define C1 64
#define C2 128
#define MU_C 0.1f
#define THR_C 0.01f

// ---------------- device scratch (allocation-free) ----------------
__device__ __half g_Wf[2 * 9 * (C2 / 8) * 256];   // fwd weights (frag order)
__device__ __half g_Wt[4 * 9 * (C1 / 8) * 256];   // tconv weights (frag order)
__device__ float  g_xn[NB * HH * WW * C1];
__device__ __half g_xr[NB * HH * WW * C1];
__device__ float  g_y [NB * HH * WW * C2];
__device__ __half g_yr[NB * HH * WW * C2];
__device__ float  g_cp[NB * HH * WW * C2];
__device__ __half g_rr[NB * HH * WW * C1];
__device__ int    g_fy[NB * 28];                  // y/yr tile-row epoch flags
__device__ int    g_fr[NB * 28];                  // rr tile-row epoch flags

__device__ __forceinline__ void mma_f16(float* d, const uint32_t* a,
                                        uint32_t b0, uint32_t b1) {
    asm volatile(
        "mma.sync.aligned.m16n8k16.row.col.f32.f16.f16.f32 "
        "{%0,%1,%2,%3}, {%4,%5,%6,%7}, {%8,%9}, {%0,%1,%2,%3};"
        : "+f"(d[0]), "+f"(d[1]), "+f"(d[2]), "+f"(d[3])
        : "r"(a[0]), "r"(a[1]), "r"(a[2]), "r"(a[3]), "r"(b0), "r"(b1));
}
__device__ __forceinline__ void ldsm_x4(uint32_t* r, uint32_t addr) {
    asm volatile("ldmatrix.sync.aligned.m8n8.x4.shared.b16 {%0,%1,%2,%3}, [%4];"
                 : "=r"(r[0]), "=r"(r[1]), "=r"(r[2]), "=r"(r[3]) : "r"(addr));
}
__device__ __forceinline__ uint32_t smem_u32(const void* p) {
    uint32_t a;
    asm("{ .reg .u64 t; cvta.to.shared.u64 t, %1; cvt.u32.u64 %0, t; }"
        : "=r"(a) : "l"(p));
    return a;
}
__device__ __forceinline__ void cp16(uint32_t dst, const void* src, int sz) {
    asm volatile("cp.async.cg.shared.global [%0], [%1], 16, %2;"
                 :: "r"(dst), "l"(src), "r"(sz));
}
__device__ __forceinline__ void cp_commit_wait() {
    asm volatile("cp.async.commit_group;");
    asm volatile("cp.async.wait_all;" ::: "memory");
}

// ---------------- prep kernels ----------------
__global__ void reset_flags_kernel() {
    int i = threadIdx.x;
    if (i < NB * 28) { g_fy[i] = 0; g_fr[i] = 0; }
}

__global__ void nchw2nhwc_kernel(const float* __restrict__ src,
                                 float* __restrict__ dfull, __half* __restrict__ rnd) {
    int i = blockIdx.x * 256 + threadIdx.x;
    int total = NB * HH * WW * C1;
    if (i >= total) return;
    int c = i & 63;
    int p = i >> 6;
    int w = p % WW;
    int q = p / WW;
    int h = q % HH;
    int n = q / HH;
    float v = src[((n * C1 + c) * HH + h) * WW + w];
    dfull[i] = v;
    rnd[i] = __float2half_rn(v);
}

__global__ void prep_w_kernel(const float* __restrict__ W) {
    const int co = blockIdx.x;
    const int tid = threadIdx.x;
    __shared__ float red[256];
    float s = 0.f;
    for (int i = tid; i < 576; i += 256) {
        float v = W[co * 576 + i];
        s += v * v;
    }
    red[tid] = s;
    __syncthreads();
    for (int off = 128; off > 0; off >>= 1) {
        if (tid < off) red[tid] += red[tid + off];
        __syncthreads();
    }
    const float inv = rsqrtf(red[0] + 1e-12f);
    for (int i = tid; i < 576; i += 256) {
        int ci = i / 9, tap = i - ci * 9;
        __half v = __float2half_rn(W[co * 576 + i] * inv);
        {   // forward: n = co, k = ci
            int k    = ci & 15;
            int kblk = (ci >> 4) & 1;
            int lane = (co & 7) * 4 + ((k & 7) >> 1);
            int reg  = (k >> 3) & 1;
            int hp   = k & 1;
            int idx  = (((ci >> 5) * 9 + tap) * (C2 / 8) + (co >> 3)) * 256 +
                       lane * 8 + kblk * 4 + reg * 2 + hp;
            g_Wf[idx] = v;
        }
        {   // transpose: n = ci, k = co, flipped tap
            int k    = co & 15;
            int kblk = (co >> 4) & 1;
            int lane = (ci & 7) * 4 + ((k & 7) >> 1);
            int reg  = (k >> 3) & 1;
            int hp   = k & 1;
            int idx  = (((co >> 5) * 9 + (8 - tap)) * (C1 / 8) + (ci >> 3)) * 256 +
                       lane * 8 + kblk * 4 + reg * 2 + hp;
            g_Wt[idx] = v;
        }
    }
}

// ---------------- one conv work item (inlined into persistent kernel) ------
// mode 0: first fwd; 1: FISTA fwd; 2: tconv+residual.  Flag dataflow as R15.
template <int CIN, int COUT>
__device__ __forceinline__ void conv_item(
    char* smem, const __half* in, const __half* wgt,
    const float* aux0, const float* aux1,
    float* out0, float* out1, __half* out2,
    float mcoef, int mode, int last,
    int n, int ty, int co0,
    const int* wflag, int wtarget, int* pflag)
{
    constexpr int STR    = CIN * 2;
    constexpr int UPR    = CIN / 8;
    constexpr int KH     = CIN / 32;
    constexpr bool BRES  = (CIN == 64);
    constexpr int BUNITS = 9 * 8 * 32;
    char* sBc = smem + 256 * STR;
    const uint32_t sAu = smem_u32(smem);
    const uint32_t sBu = sAu + 256 * STR;

    const int tid  = threadIdx.x;
    const int lane = tid & 31;
    const int w    = tid >> 5;
    const int wm   = w & 3;
    const int wn   = w >> 2;
    const int g    = lane >> 2;
    const int t    = lane & 3;
    const int h0   = ty * 2;
    const int cb0  = co0 >> 3;

    const int rb0 = wm * 32 + (lane & 7) + (lane & 8);
    const int rb1 = rb0 + 16;
    const int ulane = lane >> 4;

    __syncthreads();   // previous item fully done with smem

    // ---- stage B first (weights: stable, no dependency)
    {
        const int nun = BRES ? KH * BUNITS : BUNITS;
        for (int i = tid; i < nun; i += 256) {
            int chunk = i >> 5;
            int unit  = i & 31;
            int kt  = chunk >> 3;
            int nbl = chunk & 7;
            const __half* src = wgt + (size_t)(kt * (COUT / 8) + cb0 + nbl) * 256 + unit * 8;
            cp16(sBu + chunk * 512 + unit * 16, src, 16);
        }
    }

    // ---- wait for producer tiles (ty-1, ty, ty+1)
    if (wflag) {
        if (tid < 3) {
            int tyq = ty + tid - 1;
            if (tyq < 0) tyq = 0;
            if (tyq > 27) tyq = 27;
            const int* fp = wflag + n * 28 + tyq;
            while (true) {
                int v;
                asm volatile("ld.acquire.gpu.b32 %0, [%1];" : "=r"(v) : "l"(fp) : "memory");
                if (v >= wtarget) break;
                __nanosleep(64);
            }
        }
        __syncthreads();
        __threadfence();
    }

    // ---- stage A (entire CIN), zero-fill halo
    for (int i = tid; i < 256 * UPR; i += 256) {
        int row = i / UPR;
        int u   = i - row * UPR;
        int rr = row >> 6, cc = row & 63;
        int gh = h0 + rr - 1, gc = cc - 1;
        bool ok = ((unsigned)gh < (unsigned)HH) && ((unsigned)gc < (unsigned)WW);
        const __half* src = in +
            (size_t)((n * HH + (ok ? gh : 0)) * WW + (ok ? gc : 0)) * CIN + u * 8;
        cp16(sAu + row * STR + (((uint32_t)(u ^ (row & 7))) << 4), src, ok ? 16 : 0);
    }
    cp_commit_wait();
    __syncthreads();

    float acc[2][4][4];
#pragma unroll
    for (int c = 0; c < 2; c++)
#pragma unroll
        for (int nb = 0; nb < 4; nb++)
#pragma unroll
            for (int j = 0; j < 4; j++) acc[c][nb][j] = 0.f;

    for (int kh = 0; kh < KH; kh++) {
        if (!BRES && kh > 0) {
            __syncthreads();
            for (int i = tid; i < BUNITS; i += 256) {
                int chunk = i >> 5;
                int unit  = i & 31;
                int tap = chunk >> 3;
                int nbl = chunk & 7;
                const __half* src = wgt +
                    (size_t)((kh * 9 + tap) * (COUT / 8) + cb0 + nbl) * 256 + unit * 8;
                cp16(sBu + chunk * 512 + unit * 16, src, 16);
            }
            cp_commit_wait();
            __syncthreads();
        }

#pragma unroll 3
        for (int tap = 0; tap < 9; tap++) {
            const int ktL = (BRES ? kh * 9 + tap : tap);
            const int tapoff = (tap / 3) * 64 + (tap % 3);
            const int r0 = rb0 + tapoff;
            const int r1 = rb1 + tapoff;
            uint32_t a[2][2][4];
#pragma unroll
            for (int kblk = 0; kblk < 2; kblk++) {
                const int u = kh * 4 + kblk * 2 + ulane;
                ldsm_x4(a[0][kblk], sAu + r0 * STR + (((uint32_t)(u ^ (r0 & 7))) << 4));
                ldsm_x4(a[1][kblk], sAu + r1 * STR + (((uint32_t)(u ^ (r1 & 7))) << 4));
            }
#pragma unroll
            for (int nb = 0; nb < 4; nb++) {
                uint4 bv = *(const uint4*)(sBc +
                    (size_t)((ktL * 8 + wn * 4 + nb) * 512) + lane * 16);
                mma_f16(acc[0][nb], a[0][0], bv.x, bv.y);
                mma_f16(acc[1][nb], a[1][0], bv.x, bv.y);
                mma_f16(acc[0][nb], a[0][1], bv.z, bv.w);
                mma_f16(acc[1][nb], a[1][1], bv.z, bv.w);
            }
        }
    }

    // ---- epilogue: fused FISTA ops
#pragma unroll
    for (int c = 0; c < 2; c++) {
#pragma unroll
        for (int half = 0; half < 2; half++) {
            int m = wm * 32 + c * 16 + g + half * 8;
            int rr = m >> 6, cc = m & 63;
            if (cc >= WW) continue;
            int h = h0 + rr;
            size_t pxb = (size_t)((n * HH + h) * WW + cc) * COUT + co0;
#pragma unroll
            for (int nb = 0; nb < 4; nb++) {
                int col = wn * 32 + nb * 8 + 2 * t;
                size_t o = pxb + col;
                float v0 = acc[c][nb][half * 2 + 0];
                float v1 = acc[c][nb][half * 2 + 1];
                if (mode == 0) {
                    float2 r2;
                    r2.x = fmaxf(MU_C * v0 - THR_C, 0.f);
                    r2.y = fmaxf(MU_C * v1 - THR_C, 0.f);
                    *(float2*)(out0 + o) = r2;
                    *(float2*)(out1 + o) = r2;
                    *(half2*)(out2 + o) = __floats2half2_rn(r2.x, r2.y);
                } else if (mode == 1) {
                    float2 yv = *(const float2*)(aux0 + o);
                    float cn0 = fmaxf(yv.x + MU_C * v0 - THR_C, 0.f);
                    float cn1 = fmaxf(yv.y + MU_C * v1 - THR_C, 0.f);
                    if (last) {
                        out1[((size_t)(n * C2 + co0 + col) * HH + h) * WW + cc] = cn0;
                        out1[((size_t)(n * C2 + co0 + col + 1) * HH + h) * WW + cc] = cn1;
                    } else {
                        float2 cpv = *(const float2*)(aux1 + o);
                        float2 c2; c2.x = cn0; c2.y = cn1;
                        *(float2*)(out1 + o) = c2;
                        float2 y2;
                        y2.x = cn0 + mcoef * (cn0 - cpv.x);
                        y2.y = cn1 + mcoef * (cn1 - cpv.y);
                        *(float2*)(out0 + o) = y2;
                        *(half2*)(out2 + o) = __floats2half2_rn(y2.x, y2.y);
                    }
                } else {
                    float2 xv = *(const float2*)(aux0 + o);
                    *(half2*)(out2 + o) = __floats2half2_rn(xv.x - v0, xv.y - v1);
                }
            }
        }
    }

    // ---- publish tile flag (release)
    if (pflag) {
        __threadfence();
        __syncthreads();
        if (tid == 0) atomicAdd(pflag + n * 28 + ty, 1);
    }
}

// ---------------- persistent dataflow kernel ----------------
// Item list (phase-ordered): [0,896) fwd e0; then per k=1..5:
//   [*,+448) tconv epoch k, [*,+896) fwd epoch k.  Total 7616 items.
__global__ __launch_bounds__(256, 2)
void pconv(const __half* __restrict__ xr, const float* __restrict__ xn,
           float* __restrict__ y, __half* __restrict__ yr,
           float* __restrict__ cp, __half* __restrict__ rr,
           const __half* __restrict__ Wf, const __half* __restrict__ Wt,
           float* __restrict__ out, int* __restrict__ fy, int* __restrict__ fr,
           float m1, float m2, float m3, float m4, float m5)
{
    extern __shared__ char smem[];
    const int NITEMS = 896 + 5 * 1344;

    for (int gidx = blockIdx.x; gidx < NITEMS; gidx += gridDim.x) {
        if (gidx < 896) {
            int n = gidx / 56, r2 = gidx % 56;
            int ty = r2 >> 1, cox = r2 & 1;
            conv_item<C1, C2>(smem, xr, Wf, nullptr, nullptr, y, cp, yr,
                              0.f, 0, 0, n, ty, cox * 64, nullptr, 0, fy);
        } else {
            int gp = gidx - 896;
            int k  = gp / 1344 + 1;
            int r  = gp % 1344;
            if (r < 448) {
                int n = r / 28, ty = r % 28;
                conv_item<C2, C1>(smem, yr, Wt, xn, nullptr, nullptr, nullptr, rr,
                                  0.f, 2, 0, n, ty, 0, fy, 2 * k, fr);
            } else {
                int r2 = r - 448;
                int n = r2 / 56, q = r2 % 56;
                int ty = q >> 1, cox = q & 1;
                int last = (k == 5);
                float mc = (k == 1) ? m1 : (k == 2) ? m2 : (k == 3) ? m3
                         : (k == 4) ? m4 : m5;
                conv_item<C1, C2>(smem, rr, Wf, y, cp, y, last ? out : cp, yr,
                                  mc, 1, last, n, ty, cox * 64,
                                  fr, k, last ? nullptr : fy);
            }
        }
    }
}

// ---------------- launcher ----------------
extern "C" void kernel_launch(void* const* d_in, const int* in_sizes, int n_in,
                              void* d_out, int out_size)
{
    const float* x = (const float*)d_in[0];   // [16,64,56,56] NCHW
    const float* W = (const float*)d_in[1];   // [128,64,3,3]
    float* out = (float*)d_out;               // [16,128,56,56] NCHW

    __half *Wf, *Wt, *xr, *yr, *rr;
    float *xn, *y, *cp;
    int *fy, *fr;
    cudaGetSymbolAddress((void**)&Wf, g_Wf);
    cudaGetSymbolAddress((void**)&Wt, g_Wt);
    cudaGetSymbolAddress((void**)&xn, g_xn);
    cudaGetSymbolAddress((void**)&xr, g_xr);
    cudaGetSymbolAddress((void**)&y,  g_y);
    cudaGetSymbolAddress((void**)&yr, g_yr);
    cudaGetSymbolAddress((void**)&cp, g_cp);
    cudaGetSymbolAddress((void**)&rr, g_rr);
    cudaGetSymbolAddress((void**)&fy, g_fy);
    cudaGetSymbolAddress((void**)&fr, g_fr);

    float mv[5];
    {
        double t = 1.0;
        for (int i = 0; i < 5; i++) {
            double tn = (1.0 + sqrt(1.0 + 4.0 * t * t)) / 2.0;
            mv[i] = (float)((t - 1.0) / tn);
            t = tn;
        }
    }

    const int SMEM = 256 * (C1 * 2) + 2 * 9 * 8 * 512;   // 106496 B (max of both)
    cudaFuncSetAttribute(pconv, cudaFuncAttributeMaxDynamicSharedMemorySize, SMEM);
    cudaFuncSetAttribute(pconv, cudaFuncAttributePreferredSharedMemoryCarveout, 100);

    int nsm = 148;
    cudaDeviceGetAttribute(&nsm, cudaDevAttrMultiProcessorCount, 0);

    reset_flags_kernel<<<1, 512>>>();
    int total = NB * HH * WW * C1;
    nchw2nhwc_kernel<<<(total + 255) / 256, 256>>>(x, xn, xr);
    prep_w_kernel<<<128, 256>>>(W);

    pconv<<<2 * nsm, 256, SMEM>>>(xr, xn, y, yr, cp, rr, Wf, Wt, out, fy, fr,
                                  mv[0], mv[1], mv[2], mv[3], mv[4]);
}

// round 17
// speedup vs baseline: 1.0692x; 1.0692x over previous
#include <cuda_runtime.h>
#include <cuda_fp16.h>
#include <cstdint>
#include <math.h>

#define HH 56
#define WW 56
#define NB 16
#define C1 64
#define C2 128
#define MU_C 0.1f
#define THR_C 0.01f

// ---------------- device scratch (allocation-free) ----------------
__device__ __half g_Wf[2 * 9 * (C2 / 8) * 256];   // fwd weights (frag order)
__device__ __half g_Wt[4 * 9 * (C1 / 8) * 256];   // tconv weights (frag order)
__device__ float  g_xn[NB * HH * WW * C1];
__device__ __half g_xr[NB * HH * WW * C1];
__device__ float  g_y [NB * HH * WW * C2];
__device__ __half g_yr[NB * HH * WW * C2];
__device__ float  g_cp[NB * HH * WW * C2];
__device__ __half g_rr[NB * HH * WW * C1];
__device__ int    g_fy[NB * 28];                  // y/yr tile-row epoch flags
__device__ int    g_fr[NB * 28];                  // rr tile-row epoch flags
__device__ int    g_ctr;                          // work-stealing ticket

__device__ __forceinline__ void mma_f16(float* d, const uint32_t* a,
                                        uint32_t b0, uint32_t b1) {
    asm volatile(
        "mma.sync.aligned.m16n8k16.row.col.f32.f16.f16.f32 "
        "{%0,%1,%2,%3}, {%4,%5,%6,%7}, {%8,%9}, {%0,%1,%2,%3};"
        : "+f"(d[0]), "+f"(d[1]), "+f"(d[2]), "+f"(d[3])
        : "r"(a[0]), "r"(a[1]), "r"(a[2]), "r"(a[3]), "r"(b0), "r"(b1));
}
__device__ __forceinline__ void ldsm_x4(uint32_t* r, uint32_t addr) {
    asm volatile("ldmatrix.sync.aligned.m8n8.x4.shared.b16 {%0,%1,%2,%3}, [%4];"
                 : "=r"(r[0]), "=r"(r[1]), "=r"(r[2]), "=r"(r[3]) : "r"(addr));
}
__device__ __forceinline__ uint32_t smem_u32(const void* p) {
    uint32_t a;
    asm("{ .reg .u64 t; cvta.to.shared.u64 t, %1; cvt.u32.u64 %0, t; }"
        : "=r"(a) : "l"(p));
    return a;
}
__device__ __forceinline__ void cp16(uint32_t dst, const void* src, int sz) {
    asm volatile("cp.async.cg.shared.global [%0], [%1], 16, %2;"
                 :: "r"(dst), "l"(src), "r"(sz));
}
__device__ __forceinline__ void cp_commit_wait() {
    asm volatile("cp.async.commit_group;");
    asm volatile("cp.async.wait_all;" ::: "memory");
}

// ---------------- prep kernels ----------------
__global__ void reset_flags_kernel() {
    int i = threadIdx.x;
    if (i < NB * 28) { g_fy[i] = 0; g_fr[i] = 0; }
    if (i == 0) g_ctr = 0;
}

__global__ void nchw2nhwc_kernel(const float* __restrict__ src,
                                 float* __restrict__ dfull, __half* __restrict__ rnd) {
    int i = blockIdx.x * 256 + threadIdx.x;
    int total = NB * HH * WW * C1;
    if (i >= total) return;
    int c = i & 63;
    int p = i >> 6;
    int w = p % WW;
    int q = p / WW;
    int h = q % HH;
    int n = q / HH;
    float v = src[((n * C1 + c) * HH + h) * WW + w];
    dfull[i] = v;
    rnd[i] = __float2half_rn(v);
}

__global__ void prep_w_kernel(const float* __restrict__ W) {
    const int co = blockIdx.x;
    const int tid = threadIdx.x;
    __shared__ float red[256];
    float s = 0.f;
    for (int i = tid; i < 576; i += 256) {
        float v = W[co * 576 + i];
        s += v * v;
    }
    red[tid] = s;
    __syncthreads();
    for (int off = 128; off > 0; off >>= 1) {
        if (tid < off) red[tid] += red[tid + off];
        __syncthreads();
    }
    const float inv = rsqrtf(red[0] + 1e-12f);
    for (int i = tid; i < 576; i += 256) {
        int ci = i / 9, tap = i - ci * 9;
        __half v = __float2half_rn(W[co * 576 + i] * inv);
        {   // forward: n = co, k = ci
            int k    = ci & 15;
            int kblk = (ci >> 4) & 1;
            int lane = (co & 7) * 4 + ((k & 7) >> 1);
            int reg  = (k >> 3) & 1;
            int hp   = k & 1;
            int idx  = (((ci >> 5) * 9 + tap) * (C2 / 8) + (co >> 3)) * 256 +
                       lane * 8 + kblk * 4 + reg * 2 + hp;
            g_Wf[idx] = v;
        }
        {   // transpose: n = ci, k = co, flipped tap
            int k    = co & 15;
            int kblk = (co >> 4) & 1;
            int lane = (ci & 7) * 4 + ((k & 7) >> 1);
            int reg  = (k >> 3) & 1;
            int hp   = k & 1;
            int idx  = (((co >> 5) * 9 + (8 - tap)) * (C1 / 8) + (ci >> 3)) * 256 +
                       lane * 8 + kblk * 4 + reg * 2 + hp;
            g_Wt[idx] = v;
        }
    }
}

// ---------------- one conv work item ----------------
// mode 0: first fwd; 1: FISTA fwd; 2: tconv+residual.  Flag dataflow as R15.
template <int CIN, int COUT>
__device__ __forceinline__ void conv_item(
    char* smem, const __half* in, const __half* wgt,
    const float* aux0, const float* aux1,
    float* out0, float* out1, __half* out2,
    float mcoef, int mode, int last,
    int n, int ty, int co0,
    const int* wflag, int wtarget, int* pflag)
{
    constexpr int STR    = CIN * 2;
    constexpr int UPR    = CIN / 8;
    constexpr int KH     = CIN / 32;
    constexpr bool BRES  = (CIN == 64);
    constexpr int BUNITS = 9 * 8 * 32;
    char* sBc = smem + 256 * STR;
    const uint32_t sAu = smem_u32(smem);
    const uint32_t sBu = sAu + 256 * STR;

    const int tid  = threadIdx.x;
    const int lane = tid & 31;
    const int w    = tid >> 5;
    const int wm   = w & 3;
    const int wn   = w >> 2;
    const int g    = lane >> 2;
    const int t    = lane & 3;
    const int h0   = ty * 2;
    const int cb0  = co0 >> 3;

    const int rb0 = wm * 32 + (lane & 7) + (lane & 8);
    const int rb1 = rb0 + 16;
    const int ulane = lane >> 4;

    // ---- stage B first (weights: stable, no dependency)
    {
        const int nun = BRES ? KH * BUNITS : BUNITS;
        for (int i = tid; i < nun; i += 256) {
            int chunk = i >> 5;
            int unit  = i & 31;
            int kt  = chunk >> 3;
            int nbl = chunk & 7;
            const __half* src = wgt + (size_t)(kt * (COUT / 8) + cb0 + nbl) * 256 + unit * 8;
            cp16(sBu + chunk * 512 + unit * 16, src, 16);
        }
    }

    // ---- wait for producer tiles (ty-1, ty, ty+1)
    if (wflag) {
        if (tid < 3) {
            int tyq = ty + tid - 1;
            if (tyq < 0) tyq = 0;
            if (tyq > 27) tyq = 27;
            const int* fp = wflag + n * 28 + tyq;
            while (true) {
                int v;
                asm volatile("ld.acquire.gpu.b32 %0, [%1];" : "=r"(v) : "l"(fp) : "memory");
                if (v >= wtarget) break;
                __nanosleep(128);
            }
        }
        __syncthreads();
        __threadfence();
    }

    // ---- stage A (entire CIN), zero-fill halo
    for (int i = tid; i < 256 * UPR; i += 256) {
        int row = i / UPR;
        int u   = i - row * UPR;
        int rr = row >> 6, cc = row & 63;
        int gh = h0 + rr - 1, gc = cc - 1;
        bool ok = ((unsigned)gh < (unsigned)HH) && ((unsigned)gc < (unsigned)WW);
        const __half* src = in +
            (size_t)((n * HH + (ok ? gh : 0)) * WW + (ok ? gc : 0)) * CIN + u * 8;
        cp16(sAu + row * STR + (((uint32_t)(u ^ (row & 7))) << 4), src, ok ? 16 : 0);
    }
    cp_commit_wait();
    __syncthreads();

    float acc[2][4][4];
#pragma unroll
    for (int c = 0; c < 2; c++)
#pragma unroll
        for (int nb = 0; nb < 4; nb++)
#pragma unroll
            for (int j = 0; j < 4; j++) acc[c][nb][j] = 0.f;

    for (int kh = 0; kh < KH; kh++) {
        if (!BRES && kh > 0) {
            __syncthreads();
            for (int i = tid; i < BUNITS; i += 256) {
                int chunk = i >> 5;
                int unit  = i & 31;
                int tap = chunk >> 3;
                int nbl = chunk & 7;
                const __half* src = wgt +
                    (size_t)((kh * 9 + tap) * (COUT / 8) + cb0 + nbl) * 256 + unit * 8;
                cp16(sBu + chunk * 512 + unit * 16, src, 16);
            }
            cp_commit_wait();
            __syncthreads();
        }

#pragma unroll 3
        for (int tap = 0; tap < 9; tap++) {
            const int ktL = (BRES ? kh * 9 + tap : tap);
            const int tapoff = (tap / 3) * 64 + (tap % 3);
            const int r0 = rb0 + tapoff;
            const int r1 = rb1 + tapoff;
            uint32_t a[2][2][4];
#pragma unroll
            for (int kblk = 0; kblk < 2; kblk++) {
                const int u = kh * 4 + kblk * 2 + ulane;
                ldsm_x4(a[0][kblk], sAu + r0 * STR + (((uint32_t)(u ^ (r0 & 7))) << 4));
                ldsm_x4(a[1][kblk], sAu + r1 * STR + (((uint32_t)(u ^ (r1 & 7))) << 4));
            }
#pragma unroll
            for (int nb = 0; nb < 4; nb++) {
                uint4 bv = *(const uint4*)(sBc +
                    (size_t)((ktL * 8 + wn * 4 + nb) * 512) + lane * 16);
                mma_f16(acc[0][nb], a[0][0], bv.x, bv.y);
                mma_f16(acc[1][nb], a[1][0], bv.x, bv.y);
                mma_f16(acc[0][nb], a[0][1], bv.z, bv.w);
                mma_f16(acc[1][nb], a[1][1], bv.z, bv.w);
            }
        }
    }

    // ---- epilogue: fused FISTA ops
#pragma unroll
    for (int c = 0; c < 2; c++) {
#pragma unroll
        for (int half = 0; half < 2; half++) {
            int m = wm * 32 + c * 16 + g + half * 8;
            int rr = m >> 6, cc = m & 63;
            if (cc >= WW) continue;
            int h = h0 + rr;
            size_t pxb = (size_t)((n * HH + h) * WW + cc) * COUT + co0;
#pragma unroll
            for (int nb = 0; nb < 4; nb++) {
                int col = wn * 32 + nb * 8 + 2 * t;
                size_t o = pxb + col;
                float v0 = acc[c][nb][half * 2 + 0];
                float v1 = acc[c][nb][half * 2 + 1];
                if (mode == 0) {
                    float2 r2;
                    r2.x = fmaxf(MU_C * v0 - THR_C, 0.f);
                    r2.y = fmaxf(MU_C * v1 - THR_C, 0.f);
                    *(float2*)(out0 + o) = r2;
                    *(float2*)(out1 + o) = r2;
                    *(half2*)(out2 + o) = __floats2half2_rn(r2.x, r2.y);
                } else if (mode == 1) {
                    float2 yv = *(const float2*)(aux0 + o);
                    float cn0 = fmaxf(yv.x + MU_C * v0 - THR_C, 0.f);
                    float cn1 = fmaxf(yv.y + MU_C * v1 - THR_C, 0.f);
                    if (last) {
                        out1[((size_t)(n * C2 + co0 + col) * HH + h) * WW + cc] = cn0;
                        out1[((size_t)(n * C2 + co0 + col + 1) * HH + h) * WW + cc] = cn1;
                    } else {
                        float2 cpv = *(const float2*)(aux1 + o);
                        float2 c2; c2.x = cn0; c2.y = cn1;
                        *(float2*)(out1 + o) = c2;
                        float2 y2;
                        y2.x = cn0 + mcoef * (cn0 - cpv.x);
                        y2.y = cn1 + mcoef * (cn1 - cpv.y);
                        *(float2*)(out0 + o) = y2;
                        *(half2*)(out2 + o) = __floats2half2_rn(y2.x, y2.y);
                    }
                } else {
                    float2 xv = *(const float2*)(aux0 + o);
                    *(half2*)(out2 + o) = __floats2half2_rn(xv.x - v0, xv.y - v1);
                }
            }
        }
    }

    // ---- publish tile flag (release)
    if (pflag) {
        __threadfence();
        __syncthreads();
        if (tid == 0) atomicAdd(pflag + n * 28 + ty, 1);
    }
}

// ---------------- persistent dataflow kernel (dynamic work stealing) -------
// Phase-ordered item list: [0,896) fwd e0; per k=1..5: 448 tconv, 896 fwd.
// Items claimed via global atomic ticket -> perfect load balance; phase
// order guarantees producers are always claimed before consumers.
__global__ __launch_bounds__(256, 2)
void pconv(const __half* __restrict__ xr, const float* __restrict__ xn,
           float* __restrict__ y, __half* __restrict__ yr,
           float* __restrict__ cp, __half* __restrict__ rr,
           const __half* __restrict__ Wf, const __half* __restrict__ Wt,
           float* __restrict__ out, int* __restrict__ fy, int* __restrict__ fr,
           float m1, float m2, float m3, float m4, float m5)
{
    extern __shared__ char smem[];
    __shared__ int s_item;
    const int NITEMS = 896 + 5 * 1344;
    const int tid = threadIdx.x;

    while (true) {
        __syncthreads();                    // smem free + s_item consumed
        if (tid == 0) s_item = atomicAdd(&g_ctr, 1);
        __syncthreads();
        int gidx = s_item;
        if (gidx >= NITEMS) break;

        if (gidx < 896) {
            int n = gidx / 56, r2 = gidx % 56;
            int ty = r2 >> 1, cox = r2 & 1;
            conv_item<C1, C2>(smem, xr, Wf, nullptr, nullptr, y, cp, yr,
                              0.f, 0, 0, n, ty, cox * 64, nullptr, 0, fy);
        } else {
            int gp = gidx - 896;
            int k  = gp / 1344 + 1;
            int r  = gp % 1344;
            if (r < 448) {
                int n = r / 28, ty = r % 28;
                conv_item<C2, C1>(smem, yr, Wt, xn, nullptr, nullptr, nullptr, rr,
                                  0.f, 2, 0, n, ty, 0, fy, 2 * k, fr);
            } else {
                int r2 = r - 448;
                int n = r2 / 56, q = r2 % 56;
                int ty = q >> 1, cox = q & 1;
                int last = (k == 5);
                float mc = (k == 1) ? m1 : (k == 2) ? m2 : (k == 3) ? m3
                         : (k == 4) ? m4 : m5;
                conv_item<C1, C2>(smem, rr, Wf, y, cp, y, last ? out : cp, yr,
                                  mc, 1, last, n, ty, cox * 64,
                                  fr, k, last ? nullptr : fy);
            }
        }
    }
}

// ---------------- launcher ----------------
extern "C" void kernel_launch(void* const* d_in, const int* in_sizes, int n_in,
                              void* d_out, int out_size)
{
    const float* x = (const float*)d_in[0];   // [16,64,56,56] NCHW
    const float* W = (const float*)d_in[1];   // [128,64,3,3]
    float* out = (float*)d_out;               // [16,128,56,56] NCHW

    __half *Wf, *Wt, *xr, *yr, *rr;
    float *xn, *y, *cp;
    int *fy, *fr;
    cudaGetSymbolAddress((void**)&Wf, g_Wf);
    cudaGetSymbolAddress((void**)&Wt, g_Wt);
    cudaGetSymbolAddress((void**)&xn, g_xn);
    cudaGetSymbolAddress((void**)&xr, g_xr);
    cudaGetSymbolAddress((void**)&y,  g_y);
    cudaGetSymbolAddress((void**)&yr, g_yr);
    cudaGetSymbolAddress((void**)&cp, g_cp);
    cudaGetSymbolAddress((void**)&rr, g_rr);
    cudaGetSymbolAddress((void**)&fy, g_fy);
    cudaGetSymbolAddress((void**)&fr, g_fr);

    float mv[5];
    {
        double t = 1.0;
        for (int i = 0; i < 5; i++) {
            double tn = (1.0 + sqrt(1.0 + 4.0 * t * t)) / 2.0;
            mv[i] = (float)((t - 1.0) / tn);
            t = tn;
        }
    }

    const int SMEM = 256 * (C1 * 2) + 2 * 9 * 8 * 512;   // 106496 B (max of both)
    cudaFuncSetAttribute(pconv, cudaFuncAttributeMaxDynamicSharedMemorySize, SMEM);
    cudaFuncSetAttribute(pconv, cudaFuncAttributePreferredSharedMemoryCarveout, 100);

    int nsm = 148;
    cudaDeviceGetAttribute(&nsm, cudaDevAttrMultiProcessorCount, 0);

    reset_flags_kernel<<<1, 512>>>();
    int total = NB * HH * WW * C1;
    nchw2nhwc_kernel<<<(total + 255) / 256, 256>>>(x, xn, xr);
    prep_w_kernel<<<128, 256>>>(W);

    pconv<<<2 * nsm, 256, SMEM>>>(xr, xn, y, yr, cp, rr, Wf, Wt, out, fy, fr,
                                  mv[0], mv[1], mv[2], mv[3], mv[4]);
}